// round 4
// baseline (speedup 1.0000x reference)
#include <cuda_runtime.h>
#include <cstdint>

// PQLayer: x:(B,512) fp32, C:(64,256,8) fp32.
// Forward math collapses (see analysis): codes == one_hot(argmax_k <x_bm, C_mk>)
// exactly for non-max entries and within 1 ulp for the max entry; x_hat row ==
// C[m, kmax, :]. So: 1M independent argmax-of-256 8-dim dot products, then a
// 1.07 GB coalesced one-hot store (the DRAM-bound part).

#define FEAT 512
#define Mn   64
#define Kn   256
#define Dn   8
#define TPB  128   // threads per block = b-tiles per block

// ---- packed f32x2 helpers (Blackwell sm_103a; FFMA2 only via PTX) ----
__device__ __forceinline__ unsigned long long f2_mul(unsigned long long a,
                                                     unsigned long long b) {
    unsigned long long d;
    asm("mul.rn.f32x2 %0, %1, %2;" : "=l"(d) : "l"(a), "l"(b));
    return d;
}
__device__ __forceinline__ unsigned long long f2_fma(unsigned long long a,
                                                     unsigned long long b,
                                                     unsigned long long c) {
    unsigned long long d;
    asm("fma.rn.f32x2 %0, %1, %2, %3;" : "=l"(d) : "l"(a), "l"(b), "l"(c));
    return d;
}
__device__ __forceinline__ float2 f2_unpack(unsigned long long v) {
    float2 r;
    asm("mov.b64 {%0, %1}, %2;" : "=f"(r.x), "=f"(r.y) : "l"(v));
    return r;
}

__global__ void __launch_bounds__(TPB)
pq_kernel(const float* __restrict__ x,
          const float* __restrict__ C,
          float* __restrict__ xhat,    // may be null
          float* __restrict__ codes,   // may be null
          int nB)
{
    // C[m] tile: 256 k * 8 floats = 8 KB, as 512 x 16B (each ulonglong2 = two f32x2)
    __shared__ ulonglong2 sC[Kn * 2];
    __shared__ int s_kbest[TPB];

    const int m  = blockIdx.y;
    const int b0 = blockIdx.x * TPB;
    const int b  = b0 + threadIdx.x;

    // Stage C[m] into smem (C is tiny -> L2-resident across the 128 restages)
    const ulonglong2* Cg = reinterpret_cast<const ulonglong2*>(C + (size_t)m * Kn * Dn);
    #pragma unroll
    for (int i = threadIdx.x; i < Kn * 2; i += TPB) sC[i] = Cg[i];
    __syncthreads();

    int kbest = 0;
    if (b < nB) {
        // Load this task's 8 x-values as 4 packed f32x2 (32B, sector-aligned)
        const ulonglong2* xg =
            reinterpret_cast<const ulonglong2*>(x + (size_t)b * FEAT + m * Dn);
        ulonglong2 xl = xg[0];
        ulonglong2 xh = xg[1];
        unsigned long long xp0 = xl.x, xp1 = xl.y, xp2 = xh.x, xp3 = xh.y;

        float best = -3.4e38f;
        #pragma unroll 8
        for (int k = 0; k < Kn; ++k) {
            ulonglong2 c01 = sC[2 * k];      // broadcast LDS (all lanes same m,k)
            ulonglong2 c23 = sC[2 * k + 1];
            unsigned long long acc = f2_mul(xp0, c01.x);
            acc = f2_fma(xp1, c01.y, acc);
            acc = f2_fma(xp2, c23.x, acc);
            acc = f2_fma(xp3, c23.y, acc);
            float2 ab = f2_unpack(acc);
            float dot = ab.x + ab.y;
            if (dot > best) { best = dot; kbest = k; }   // strict > => first index on ties
        }

        // x_hat row = C[m, kbest, :]  (codes value at max is 1 to within 1 ulp)
        if (xhat) {
            ulonglong2* o =
                reinterpret_cast<ulonglong2*>(xhat + (size_t)b * FEAT + m * Dn);
            o[0] = sC[2 * kbest];
            o[1] = sC[2 * kbest + 1];
        }
    }

    // One-hot codes rows, block-cooperative fully-coalesced float4 stores.
    if (codes) {
        s_kbest[threadIdx.x] = kbest;
        __syncthreads();
        // 128 rows * 64 float4 per row; consecutive threads -> consecutive float4
        float4* base = reinterpret_cast<float4*>(codes) +
                       (((size_t)b0 * Mn + m) * Kn) / 4;
        const size_t row_stride4 = (size_t)Mn * Kn / 4;   // 4096 float4 between rows
        #pragma unroll 4
        for (int i = threadIdx.x; i < TPB * (Kn / 4); i += TPB) {
            int r  = i >> 6;          // task row within block
            int c4 = i & 63;          // float4 index within row
            if (b0 + r >= nB) break;
            int kb = s_kbest[r];
            int c  = c4 * 4;
            float4 v;
            v.x = (kb == c + 0) ? 1.0f : 0.0f;
            v.y = (kb == c + 1) ? 1.0f : 0.0f;
            v.z = (kb == c + 2) ? 1.0f : 0.0f;
            v.w = (kb == c + 3) ? 1.0f : 0.0f;
            base[(size_t)r * row_stride4 + c4] = v;
        }
    }
}

extern "C" void kernel_launch(void* const* d_in, const int* in_sizes, int n_in,
                              void* d_out, int out_size)
{
    // Resolve inputs by size: x has B*512 elems, C has 64*256*8 = 131072 elems.
    const float* x = (const float*)d_in[0];
    const float* C = (const float*)d_in[1];
    int x_size = in_sizes[0];
    if (n_in >= 2 && in_sizes[0] == Mn * Kn * Dn && in_sizes[1] != Mn * Kn * Dn) {
        x = (const float*)d_in[1];
        C = (const float*)d_in[0];
        x_size = in_sizes[1];
    }
    const int nB = x_size / FEAT;

    const long long XH = (long long)nB * FEAT;        // x_hat elems
    const long long CD = (long long)nB * Mn * Kn;     // codes elems

    float* out  = (float*)d_out;
    float* xhat  = nullptr;
    float* codes = nullptr;
    if ((long long)out_size == XH + CD)      { xhat = out; codes = out + XH; }
    else if ((long long)out_size == XH)      { xhat = out; }
    else if ((long long)out_size == CD)      { codes = out; }
    else                                     { xhat = out; codes = out + XH; } // default: tuple order

    dim3 grid((nB + TPB - 1) / TPB, Mn);
    pq_kernel<<<grid, TPB>>>(x, C, xhat, codes, nB);
}